// round 5
// baseline (speedup 1.0000x reference)
#include <cuda_runtime.h>

#define NN 50000
#define DD 128
#define EE 800000
#define NBLK 782          // GEMM row-tile blocks: ceil(50000/64)

// ---------------- scratch (device globals: no allocs allowed) ----------------
__device__ __align__(16) float g_comb[NN * DD];  // combined features (gather output)
__device__ __align__(16) float g_h[NN * DD];     // post-Linear1 activations
__device__ __align__(16) float g_x[NN * DD];     // layer output ping buffer
__device__ float g_psum[NBLK * DD];
__device__ float g_psumsq[NBLK * DD];
__device__ float g_scale[DD];
__device__ float g_shift[DD];
// CSR (built once per call, reused across layers)
__device__ int g_cnt[NN];
__device__ int g_row[NN + 1];
__device__ int g_cur[NN];
__device__ int g_adj[EE];

// ---------------- CSR build ----------------
__global__ void k_zero_cnt() {
    int i = blockIdx.x * blockDim.x + threadIdx.x;
    if (i < NN) g_cnt[i] = 0;
}

__global__ void k_hist(const int* __restrict__ dst) {
    int e = blockIdx.x * blockDim.x + threadIdx.x;
    if (e < EE) atomicAdd(&g_cnt[dst[e]], 1);
}

// single block, 1024 threads: exclusive prefix sum of g_cnt -> g_row, zero g_cur
__global__ void __launch_bounds__(1024) k_scan() {
    __shared__ int sm[1024];
    const int CH = 49;  // 1024*49 >= 50000
    int t = threadIdx.x;
    int beg = t * CH;
    int tot = 0;
    for (int i = beg; i < beg + CH && i < NN; i++) tot += g_cnt[i];
    sm[t] = tot;
    __syncthreads();
    for (int off = 1; off < 1024; off <<= 1) {
        int v = (t >= off) ? sm[t - off] : 0;
        __syncthreads();
        sm[t] += v;
        __syncthreads();
    }
    int base = sm[t] - tot;  // exclusive
    for (int i = beg; i < beg + CH && i < NN; i++) {
        g_row[i] = base;
        g_cur[i] = 0;
        base += g_cnt[i];
    }
    if (t == 1023) g_row[NN] = sm[1023];
}

__global__ void k_fill(const int* __restrict__ src,
                       const int* __restrict__ dst) {
    int e = blockIdx.x * blockDim.x + threadIdx.x;
    if (e >= EE) return;
    int d = dst[e];
    int pos = atomicAdd(&g_cur[d], 1);
    g_adj[g_row[d] + pos] = src[e];
}

// ---------------- gather + combine: warp per node ----------------
// agg = sum_{j in adj(node)} x_j ; out = l2norm(agg) + (1+eps)*l2norm(x_node)
__global__ void k_gather(const float* __restrict__ Xext, int use_ext,
                         const float* __restrict__ epsp) {
    const float* X = use_ext ? Xext : (const float*)g_x;
    int gid = blockIdx.x * blockDim.x + threadIdx.x;
    int node = gid >> 5;
    if (node >= NN) return;
    int lane = gid & 31;
    int beg = g_row[node], end = g_row[node + 1];
    float4 a = make_float4(0.f, 0.f, 0.f, 0.f);
    for (int i = beg; i < end; i++) {
        int s = g_adj[i];
        float4 v = ((const float4*)X)[s * 32 + lane];
        a.x += v.x; a.y += v.y; a.z += v.z; a.w += v.w;
    }
    float4 xv = ((const float4*)X)[node * 32 + lane];
    float pa = a.x * a.x + a.y * a.y + a.z * a.z + a.w * a.w;
    float px = xv.x * xv.x + xv.y * xv.y + xv.z * xv.z + xv.w * xv.w;
    #pragma unroll
    for (int off = 16; off; off >>= 1) {
        pa += __shfl_xor_sync(0xffffffffu, pa, off);
        px += __shfl_xor_sync(0xffffffffu, px, off);
    }
    float ia = 1.f / fmaxf(sqrtf(pa), 1e-12f);
    float ix = (1.f + epsp[0]) / fmaxf(sqrtf(px), 1e-12f);
    float4 o;
    o.x = a.x * ia + xv.x * ix;
    o.y = a.y * ia + xv.y * ix;
    o.z = a.z * ia + xv.z * ix;
    o.w = a.w * ia + xv.w * ix;
    ((float4*)g_comb)[node * 32 + lane] = o;
}

// ---------------- GEMM1: h = comb @ W1 + b1 -> g_h, per-block BN partials ----------------
// 256 threads, 64 rows/block. Static smem: Xs 32KB + Ws chunk 16KB = 48KB.
__global__ void __launch_bounds__(256) k_gemm1(const float* __restrict__ W,
                                               const float* __restrict__ b) {
    __shared__ float Ws[32 * DD];
    __shared__ float Xs[64 * DD];
    int tid = threadIdx.x;
    int row0 = blockIdx.x * 64;
    int warp = tid >> 5, lane = tid & 31;

    for (int i = tid; i < 2048; i += 256) {
        int r = i >> 5, c = i & 31;
        int gr = row0 + r;
        float4 v = make_float4(0.f, 0.f, 0.f, 0.f);
        if (gr < NN) v = ((const float4*)g_comb)[gr * 32 + c];
        ((float4*)Xs)[i] = v;
    }

    float4 acc[8];
    #pragma unroll
    for (int r = 0; r < 8; r++) acc[r] = make_float4(0.f, 0.f, 0.f, 0.f);
    const float* xb = Xs + warp * 8 * DD;

    for (int ch = 0; ch < 4; ch++) {
        __syncthreads();
        for (int i = tid; i < 1024; i += 256)
            ((float4*)Ws)[i] = ((const float4*)W)[ch * 1024 + i];
        __syncthreads();
        #pragma unroll 4
        for (int kk = 0; kk < 32; kk++) {
            float4 w = ((const float4*)Ws)[kk * 32 + lane];
            int k = ch * 32 + kk;
            #pragma unroll
            for (int r = 0; r < 8; r++) {
                float xv = xb[r * DD + k];
                acc[r].x = fmaf(xv, w.x, acc[r].x);
                acc[r].y = fmaf(xv, w.y, acc[r].y);
                acc[r].z = fmaf(xv, w.z, acc[r].z);
                acc[r].w = fmaf(xv, w.w, acc[r].w);
            }
        }
    }
    __syncthreads();  // before reusing Xs as stats scratch

    float4 bias = ((const float4*)b)[lane];
    float4 ls = make_float4(0.f, 0.f, 0.f, 0.f);
    float4 lq = make_float4(0.f, 0.f, 0.f, 0.f);
    #pragma unroll
    for (int r = 0; r < 8; r++) {
        int gr = row0 + warp * 8 + r;
        if (gr < NN) {
            float4 h;
            h.x = acc[r].x + bias.x; h.y = acc[r].y + bias.y;
            h.z = acc[r].z + bias.z; h.w = acc[r].w + bias.w;
            ((float4*)g_h)[gr * 32 + lane] = h;
            ls.x += h.x; ls.y += h.y; ls.z += h.z; ls.w += h.w;
            lq.x += h.x * h.x; lq.y += h.y * h.y; lq.z += h.z * h.z; lq.w += h.w * h.w;
        }
    }
    float* S = Xs;
    float* Q = Xs + 8 * DD;
    int col = lane * 4;
    S[warp * DD + col + 0] = ls.x; S[warp * DD + col + 1] = ls.y;
    S[warp * DD + col + 2] = ls.z; S[warp * DD + col + 3] = ls.w;
    Q[warp * DD + col + 0] = lq.x; Q[warp * DD + col + 1] = lq.y;
    Q[warp * DD + col + 2] = lq.z; Q[warp * DD + col + 3] = lq.w;
    __syncthreads();
    if (tid < DD) {
        float s = 0.f, q = 0.f;
        #pragma unroll
        for (int w2 = 0; w2 < 8; w2++) { s += S[w2 * DD + tid]; q += Q[w2 * DD + tid]; }
        g_psum[blockIdx.x * DD + tid] = s;       // per-block partial, no atomics
        g_psumsq[blockIdx.x * DD + tid] = q;
    }
}

// ---------------- finalize BN: 128 blocks (one per channel) reduce partials ----------------
__global__ void __launch_bounds__(256) k_finalize(const float* __restrict__ gamma,
                                                  const float* __restrict__ beta) {
    __shared__ float ss[256], sq[256];
    int c = blockIdx.x;
    int t = threadIdx.x;
    float s = 0.f, q = 0.f;
    for (int bk = t; bk < NBLK; bk += 256) {
        s += g_psum[bk * DD + c];
        q += g_psumsq[bk * DD + c];
    }
    ss[t] = s; sq[t] = q;
    __syncthreads();
    for (int off = 128; off; off >>= 1) {
        if (t < off) { ss[t] += ss[t + off]; sq[t] += sq[t + off]; }
        __syncthreads();
    }
    if (t == 0) {
        float mean = ss[0] * (1.f / NN);
        float var  = sq[0] * (1.f / NN) - mean * mean;
        float sc = gamma[c] * rsqrtf(var + 1e-5f);
        g_scale[c] = sc;
        g_shift[c] = beta[c] - mean * sc;
    }
}

// ---------------- GEMM2: out = relu?(bn_relu(h) @ W2 + b2) ----------------
__global__ void __launch_bounds__(256) k_gemm2(const float* __restrict__ W,
                                               const float* __restrict__ b,
                                               float* __restrict__ OutExt,
                                               int internal, int do_relu) {
    __shared__ float Ws[32 * DD];
    __shared__ float Xs[64 * DD];
    float* Out = internal ? (float*)g_x : OutExt;
    int tid = threadIdx.x;
    int row0 = blockIdx.x * 64;
    int warp = tid >> 5, lane = tid & 31;

    for (int i = tid; i < 2048; i += 256) {
        int r = i >> 5, c = i & 31;
        int gr = row0 + r;
        float4 v = make_float4(0.f, 0.f, 0.f, 0.f);
        if (gr < NN) {
            float4 h  = ((const float4*)g_h)[gr * 32 + c];
            float4 sc = ((const float4*)g_scale)[c];
            float4 sf = ((const float4*)g_shift)[c];
            v.x = fmaxf(fmaf(h.x, sc.x, sf.x), 0.f);
            v.y = fmaxf(fmaf(h.y, sc.y, sf.y), 0.f);
            v.z = fmaxf(fmaf(h.z, sc.z, sf.z), 0.f);
            v.w = fmaxf(fmaf(h.w, sc.w, sf.w), 0.f);
        }
        ((float4*)Xs)[i] = v;
    }

    float4 acc[8];
    #pragma unroll
    for (int r = 0; r < 8; r++) acc[r] = make_float4(0.f, 0.f, 0.f, 0.f);
    const float* xb = Xs + warp * 8 * DD;

    for (int ch = 0; ch < 4; ch++) {
        __syncthreads();
        for (int i = tid; i < 1024; i += 256)
            ((float4*)Ws)[i] = ((const float4*)W)[ch * 1024 + i];
        __syncthreads();
        #pragma unroll 4
        for (int kk = 0; kk < 32; kk++) {
            float4 w = ((const float4*)Ws)[kk * 32 + lane];
            int k = ch * 32 + kk;
            #pragma unroll
            for (int r = 0; r < 8; r++) {
                float xv = xb[r * DD + k];
                acc[r].x = fmaf(xv, w.x, acc[r].x);
                acc[r].y = fmaf(xv, w.y, acc[r].y);
                acc[r].z = fmaf(xv, w.z, acc[r].z);
                acc[r].w = fmaf(xv, w.w, acc[r].w);
            }
        }
    }

    float4 bias = ((const float4*)b)[lane];
    #pragma unroll
    for (int r = 0; r < 8; r++) {
        int gr = row0 + warp * 8 + r;
        if (gr < NN) {
            float4 o;
            o.x = acc[r].x + bias.x; o.y = acc[r].y + bias.y;
            o.z = acc[r].z + bias.z; o.w = acc[r].w + bias.w;
            if (do_relu) {
                o.x = fmaxf(o.x, 0.f); o.y = fmaxf(o.y, 0.f);
                o.z = fmaxf(o.z, 0.f); o.w = fmaxf(o.w, 0.f);
            }
            ((float4*)Out)[gr * 32 + lane] = o;
        }
    }
}

extern "C" void kernel_launch(void* const* d_in, const int* in_sizes, int n_in,
                              void* d_out, int out_size) {
    (void)in_sizes; (void)n_in; (void)out_size;
    const float* x     = (const float*)d_in[0];
    const int*   ei    = (const int*)d_in[1];   // int32! (JAX x64 disabled downcasts int64)
    const float* W1    = (const float*)d_in[2];
    const float* b1    = (const float*)d_in[3];
    const float* gamma = (const float*)d_in[4];
    const float* beta  = (const float*)d_in[5];
    const float* W2    = (const float*)d_in[6];
    const float* b2    = (const float*)d_in[7];
    const float* eps   = (const float*)d_in[8];
    float* out = (float*)d_out;

    const int* src = ei;
    const int* dst = ei + EE;

    // CSR build (once, reused across the 3 layers)
    k_zero_cnt<<<(NN + 255) / 256, 256>>>();
    k_hist<<<(EE + 255) / 256, 256>>>(dst);
    k_scan<<<1, 1024>>>();
    k_fill<<<(EE + 255) / 256, 256>>>(src, dst);

    for (int l = 0; l < 3; l++) {
        int use_ext = (l == 0) ? 1 : 0;
        int internal = (l == 2) ? 0 : 1;
        k_gather<<<(NN * 32 + 255) / 256, 256>>>(x, use_ext, eps + l);
        k_gemm1<<<NBLK, 256>>>(W1 + l * DD * DD, b1 + l * DD);
        k_finalize<<<DD, 256>>>(gamma + l * DD, beta + l * DD);
        k_gemm2<<<NBLK, 256>>>(W2 + l * DD * DD, b2 + l * DD, out, internal, (l < 2) ? 1 : 0);
    }
}

// round 6
// speedup vs baseline: 1.0130x; 1.0130x over previous
#include <cuda_runtime.h>

#define NN 50000
#define DD 128
#define EE 800000
#define NBLK 782          // GEMM row-tile blocks: ceil(50000/64)

// ---------------- scratch (device globals: no allocs allowed) ----------------
__device__ __align__(16) float g_comb[NN * DD];  // combined features (gather output)
__device__ __align__(16) float g_h[NN * DD];     // post-Linear1 activations
__device__ __align__(16) float g_x[NN * DD];     // layer output ping buffer
__device__ float g_psum[NBLK * DD];
__device__ float g_psumsq[NBLK * DD];
__device__ float g_scale[DD];
__device__ float g_shift[DD];
// CSR (built once per call, reused across layers)
__device__ int g_cnt[NN];
__device__ int g_row[NN + 1];
__device__ int g_cur[NN];
__device__ int g_adj[EE];

// ---------------- packed fp32x2 helpers (sm_103a FFMA2 path) ----------------
__device__ __forceinline__ unsigned long long pack2(float lo, float hi) {
    unsigned long long r;
    asm("mov.b64 %0, {%1, %2};" : "=l"(r) : "f"(lo), "f"(hi));
    return r;
}
__device__ __forceinline__ unsigned long long fma2(unsigned long long a,
                                                   unsigned long long b,
                                                   unsigned long long c) {
    unsigned long long d;
    asm("fma.rn.f32x2 %0, %1, %2, %3;" : "=l"(d) : "l"(a), "l"(b), "l"(c));
    return d;
}
__device__ __forceinline__ float2 unpack2(unsigned long long v) {
    float lo, hi;
    asm("mov.b64 {%0, %1}, %2;" : "=f"(lo), "=f"(hi) : "l"(v));
    return make_float2(lo, hi);
}

// ---------------- CSR build ----------------
__global__ void k_zero_cnt() {
    int i = blockIdx.x * blockDim.x + threadIdx.x;
    if (i < NN) g_cnt[i] = 0;
}

__global__ void k_hist(const int* __restrict__ dst) {
    int e = blockIdx.x * blockDim.x + threadIdx.x;
    if (e < EE) atomicAdd(&g_cnt[dst[e]], 1);
}

// single block, 1024 threads: exclusive prefix sum of g_cnt -> g_row, zero g_cur
__global__ void __launch_bounds__(1024) k_scan() {
    __shared__ int sm[1024];
    const int CH = 49;  // 1024*49 >= 50000
    int t = threadIdx.x;
    int beg = t * CH;
    int tot = 0;
    for (int i = beg; i < beg + CH && i < NN; i++) tot += g_cnt[i];
    sm[t] = tot;
    __syncthreads();
    for (int off = 1; off < 1024; off <<= 1) {
        int v = (t >= off) ? sm[t - off] : 0;
        __syncthreads();
        sm[t] += v;
        __syncthreads();
    }
    int base = sm[t] - tot;  // exclusive
    for (int i = beg; i < beg + CH && i < NN; i++) {
        g_row[i] = base;
        g_cur[i] = 0;
        base += g_cnt[i];
    }
    if (t == 1023) g_row[NN] = sm[1023];
}

__global__ void k_fill(const int* __restrict__ src,
                       const int* __restrict__ dst) {
    int e = blockIdx.x * blockDim.x + threadIdx.x;
    if (e >= EE) return;
    int d = dst[e];
    int pos = atomicAdd(&g_cur[d], 1);
    g_adj[g_row[d] + pos] = src[e];
}

// ---------------- gather + combine: warp per node ----------------
__global__ void k_gather(const float* __restrict__ Xext, int use_ext,
                         const float* __restrict__ epsp) {
    const float* X = use_ext ? Xext : (const float*)g_x;
    int gid = blockIdx.x * blockDim.x + threadIdx.x;
    int node = gid >> 5;
    if (node >= NN) return;
    int lane = gid & 31;
    int beg = g_row[node], end = g_row[node + 1];
    float4 a = make_float4(0.f, 0.f, 0.f, 0.f);
    for (int i = beg; i < end; i++) {
        int s = g_adj[i];
        float4 v = ((const float4*)X)[s * 32 + lane];
        a.x += v.x; a.y += v.y; a.z += v.z; a.w += v.w;
    }
    float4 xv = ((const float4*)X)[node * 32 + lane];
    float pa = a.x * a.x + a.y * a.y + a.z * a.z + a.w * a.w;
    float px = xv.x * xv.x + xv.y * xv.y + xv.z * xv.z + xv.w * xv.w;
    #pragma unroll
    for (int off = 16; off; off >>= 1) {
        pa += __shfl_xor_sync(0xffffffffu, pa, off);
        px += __shfl_xor_sync(0xffffffffu, px, off);
    }
    float ia = 1.f / fmaxf(sqrtf(pa), 1e-12f);
    float ix = (1.f + epsp[0]) / fmaxf(sqrtf(px), 1e-12f);
    float4 o;
    o.x = a.x * ia + xv.x * ix;
    o.y = a.y * ia + xv.y * ix;
    o.z = a.z * ia + xv.z * ix;
    o.w = a.w * ia + xv.w * ix;
    ((float4*)g_comb)[node * 32 + lane] = o;
}

// ---------------- GEMM1: h = comb @ W1 + b1 -> g_h, per-block BN partials ----------------
// 256 threads, 64 rows/block. Xs in row-pair-interleaved layout for f32x2 FMA.
__global__ void __launch_bounds__(256) k_gemm1(const float* __restrict__ W,
                                               const float* __restrict__ b) {
    __shared__ float Ws[32 * DD];
    __shared__ float Xs[64 * DD];   // Xs[(rp*DD + k)*2 + j] = x[2rp+j][k]
    int tid = threadIdx.x;
    int row0 = blockIdx.x * 64;
    int warp = tid >> 5, lane = tid & 31;

    for (int i = tid; i < 2048; i += 256) {
        int r = i >> 5, c = i & 31;
        int gr = row0 + r;
        float4 v = make_float4(0.f, 0.f, 0.f, 0.f);
        if (gr < NN) v = ((const float4*)g_comb)[gr * 32 + c];
        int rp = r >> 1, j = r & 1;
        float* p = Xs + (rp * DD + 4 * c) * 2 + j;
        p[0] = v.x; p[2] = v.y; p[4] = v.z; p[6] = v.w;
    }

    unsigned long long acc[4][4];
    #pragma unroll
    for (int rp = 0; rp < 4; rp++)
        #pragma unroll
        for (int c = 0; c < 4; c++) acc[rp][c] = 0ull;
    const float* xp = Xs + warp * 4 * DD * 2;

    for (int ch = 0; ch < 4; ch++) {
        __syncthreads();
        for (int i = tid; i < 1024; i += 256)
            ((float4*)Ws)[i] = ((const float4*)W)[ch * 1024 + i];
        __syncthreads();
        #pragma unroll 4
        for (int kk = 0; kk < 32; kk++) {
            int k = ch * 32 + kk;
            float4 w = ((const float4*)Ws)[kk * 32 + lane];
            unsigned long long w2x = pack2(w.x, w.x);
            unsigned long long w2y = pack2(w.y, w.y);
            unsigned long long w2z = pack2(w.z, w.z);
            unsigned long long w2w = pack2(w.w, w.w);
            #pragma unroll
            for (int rp = 0; rp < 4; rp++) {
                unsigned long long x2 =
                    *(const unsigned long long*)(xp + (rp * DD + k) * 2);
                acc[rp][0] = fma2(x2, w2x, acc[rp][0]);
                acc[rp][1] = fma2(x2, w2y, acc[rp][1]);
                acc[rp][2] = fma2(x2, w2z, acc[rp][2]);
                acc[rp][3] = fma2(x2, w2w, acc[rp][3]);
            }
        }
    }
    __syncthreads();  // before reusing Xs as stats scratch

    float4 bias = ((const float4*)b)[lane];
    float4 ls = make_float4(0.f, 0.f, 0.f, 0.f);
    float4 lq = make_float4(0.f, 0.f, 0.f, 0.f);
    #pragma unroll
    for (int rp = 0; rp < 4; rp++) {
        float2 ax = unpack2(acc[rp][0]);
        float2 ay = unpack2(acc[rp][1]);
        float2 az = unpack2(acc[rp][2]);
        float2 aw = unpack2(acc[rp][3]);
        int gr0 = row0 + warp * 8 + rp * 2;
        if (gr0 < NN) {
            float4 h;
            h.x = ax.x + bias.x; h.y = ay.x + bias.y;
            h.z = az.x + bias.z; h.w = aw.x + bias.w;
            ((float4*)g_h)[gr0 * 32 + lane] = h;
            ls.x += h.x; ls.y += h.y; ls.z += h.z; ls.w += h.w;
            lq.x += h.x * h.x; lq.y += h.y * h.y; lq.z += h.z * h.z; lq.w += h.w * h.w;
        }
        int gr1 = gr0 + 1;
        if (gr1 < NN) {
            float4 h;
            h.x = ax.y + bias.x; h.y = ay.y + bias.y;
            h.z = az.y + bias.z; h.w = aw.y + bias.w;
            ((float4*)g_h)[gr1 * 32 + lane] = h;
            ls.x += h.x; ls.y += h.y; ls.z += h.z; ls.w += h.w;
            lq.x += h.x * h.x; lq.y += h.y * h.y; lq.z += h.z * h.z; lq.w += h.w * h.w;
        }
    }
    float* S = Xs;
    float* Q = Xs + 8 * DD;
    int col = lane * 4;
    S[warp * DD + col + 0] = ls.x; S[warp * DD + col + 1] = ls.y;
    S[warp * DD + col + 2] = ls.z; S[warp * DD + col + 3] = ls.w;
    Q[warp * DD + col + 0] = lq.x; Q[warp * DD + col + 1] = lq.y;
    Q[warp * DD + col + 2] = lq.z; Q[warp * DD + col + 3] = lq.w;
    __syncthreads();
    if (tid < DD) {
        float s = 0.f, q = 0.f;
        #pragma unroll
        for (int w2 = 0; w2 < 8; w2++) { s += S[w2 * DD + tid]; q += Q[w2 * DD + tid]; }
        g_psum[blockIdx.x * DD + tid] = s;
        g_psumsq[blockIdx.x * DD + tid] = q;
    }
}

// ---------------- finalize BN: 128 blocks (one per channel) reduce partials ----------------
__global__ void __launch_bounds__(256) k_finalize(const float* __restrict__ gamma,
                                                  const float* __restrict__ beta) {
    __shared__ float ss[256], sq[256];
    int c = blockIdx.x;
    int t = threadIdx.x;
    float s = 0.f, q = 0.f;
    for (int bk = t; bk < NBLK; bk += 256) {
        s += g_psum[bk * DD + c];
        q += g_psumsq[bk * DD + c];
    }
    ss[t] = s; sq[t] = q;
    __syncthreads();
    for (int off = 128; off; off >>= 1) {
        if (t < off) { ss[t] += ss[t + off]; sq[t] += sq[t + off]; }
        __syncthreads();
    }
    if (t == 0) {
        float mean = ss[0] * (1.f / NN);
        float var  = sq[0] * (1.f / NN) - mean * mean;
        float sc = gamma[c] * rsqrtf(var + 1e-5f);
        g_scale[c] = sc;
        g_shift[c] = beta[c] - mean * sc;
    }
}

// ---------------- GEMM2: out = relu?(bn_relu(h) @ W2 + b2) ----------------
__global__ void __launch_bounds__(256) k_gemm2(const float* __restrict__ W,
                                               const float* __restrict__ b,
                                               float* __restrict__ OutExt,
                                               int internal, int do_relu) {
    __shared__ float Ws[32 * DD];
    __shared__ float Xs[64 * DD];   // row-pair interleaved
    float* Out = internal ? (float*)g_x : OutExt;
    int tid = threadIdx.x;
    int row0 = blockIdx.x * 64;
    int warp = tid >> 5, lane = tid & 31;

    for (int i = tid; i < 2048; i += 256) {
        int r = i >> 5, c = i & 31;
        int gr = row0 + r;
        float4 v = make_float4(0.f, 0.f, 0.f, 0.f);
        if (gr < NN) {
            float4 h  = ((const float4*)g_h)[gr * 32 + c];
            float4 sc = ((const float4*)g_scale)[c];
            float4 sf = ((const float4*)g_shift)[c];
            v.x = fmaxf(fmaf(h.x, sc.x, sf.x), 0.f);
            v.y = fmaxf(fmaf(h.y, sc.y, sf.y), 0.f);
            v.z = fmaxf(fmaf(h.z, sc.z, sf.z), 0.f);
            v.w = fmaxf(fmaf(h.w, sc.w, sf.w), 0.f);
        }
        int rp = r >> 1, j = r & 1;
        float* p = Xs + (rp * DD + 4 * c) * 2 + j;
        p[0] = v.x; p[2] = v.y; p[4] = v.z; p[6] = v.w;
    }

    unsigned long long acc[4][4];
    #pragma unroll
    for (int rp = 0; rp < 4; rp++)
        #pragma unroll
        for (int c = 0; c < 4; c++) acc[rp][c] = 0ull;
    const float* xp = Xs + warp * 4 * DD * 2;

    for (int ch = 0; ch < 4; ch++) {
        __syncthreads();
        for (int i = tid; i < 1024; i += 256)
            ((float4*)Ws)[i] = ((const float4*)W)[ch * 1024 + i];
        __syncthreads();
        #pragma unroll 4
        for (int kk = 0; kk < 32; kk++) {
            int k = ch * 32 + kk;
            float4 w = ((const float4*)Ws)[kk * 32 + lane];
            unsigned long long w2x = pack2(w.x, w.x);
            unsigned long long w2y = pack2(w.y, w.y);
            unsigned long long w2z = pack2(w.z, w.z);
            unsigned long long w2w = pack2(w.w, w.w);
            #pragma unroll
            for (int rp = 0; rp < 4; rp++) {
                unsigned long long x2 =
                    *(const unsigned long long*)(xp + (rp * DD + k) * 2);
                acc[rp][0] = fma2(x2, w2x, acc[rp][0]);
                acc[rp][1] = fma2(x2, w2y, acc[rp][1]);
                acc[rp][2] = fma2(x2, w2z, acc[rp][2]);
                acc[rp][3] = fma2(x2, w2w, acc[rp][3]);
            }
        }
    }

    float4 bias = ((const float4*)b)[lane];
    #pragma unroll
    for (int rp = 0; rp < 4; rp++) {
        float2 ax = unpack2(acc[rp][0]);
        float2 ay = unpack2(acc[rp][1]);
        float2 az = unpack2(acc[rp][2]);
        float2 aw = unpack2(acc[rp][3]);
        #pragma unroll
        for (int j = 0; j < 2; j++) {
            int gr = row0 + warp * 8 + rp * 2 + j;
            if (gr < NN) {
                float4 o;
                o.x = (j ? ax.y : ax.x) + bias.x;
                o.y = (j ? ay.y : ay.x) + bias.y;
                o.z = (j ? az.y : az.x) + bias.z;
                o.w = (j ? aw.y : aw.x) + bias.w;
                if (do_relu) {
                    o.x = fmaxf(o.x, 0.f); o.y = fmaxf(o.y, 0.f);
                    o.z = fmaxf(o.z, 0.f); o.w = fmaxf(o.w, 0.f);
                }
                ((float4*)Out)[gr * 32 + lane] = o;
            }
        }
    }
}

extern "C" void kernel_launch(void* const* d_in, const int* in_sizes, int n_in,
                              void* d_out, int out_size) {
    (void)in_sizes; (void)n_in; (void)out_size;
    const float* x     = (const float*)d_in[0];
    const int*   ei    = (const int*)d_in[1];   // int32 (JAX x64 disabled)
    const float* W1    = (const float*)d_in[2];
    const float* b1    = (const float*)d_in[3];
    const float* gamma = (const float*)d_in[4];
    const float* beta  = (const float*)d_in[5];
    const float* W2    = (const float*)d_in[6];
    const float* b2    = (const float*)d_in[7];
    const float* eps   = (const float*)d_in[8];
    float* out = (float*)d_out;

    const int* src = ei;
    const int* dst = ei + EE;

    // CSR build (once, reused across the 3 layers)
    k_zero_cnt<<<(NN + 255) / 256, 256>>>();
    k_hist<<<(EE + 255) / 256, 256>>>(dst);
    k_scan<<<1, 1024>>>();
    k_fill<<<(EE + 255) / 256, 256>>>(src, dst);

    for (int l = 0; l < 3; l++) {
        int use_ext = (l == 0) ? 1 : 0;
        int internal = (l == 2) ? 0 : 1;
        k_gather<<<(NN * 32 + 255) / 256, 256>>>(x, use_ext, eps + l);
        k_gemm1<<<NBLK, 256>>>(W1 + l * DD * DD, b1 + l * DD);
        k_finalize<<<DD, 256>>>(gamma + l * DD, beta + l * DD);
        k_gemm2<<<NBLK, 256>>>(W2 + l * DD * DD, b2 + l * DD, out, internal, (l < 2) ? 1 : 0);
    }
}

// round 8
// speedup vs baseline: 1.1941x; 1.1788x over previous
#include <cuda_runtime.h>
#include <cuda_bf16.h>
#include <cstdint>

#define NN 50000
#define DD 128
#define EE 800000
#define NBT 391           // ceil(50000/128) GEMM row tiles

typedef unsigned short ushortt;

// ---------------- scratch (device globals: no allocs allowed) ----------------
__device__ __align__(16) float g_comb[NN * DD];
__device__ __align__(16) float g_h[NN * DD];
__device__ __align__(16) float g_x[NN * DD];
__device__ float g_psum[NBT * DD];
__device__ float g_psumsq[NBT * DD];
__device__ float g_scale[DD];
__device__ float g_shift[DD];
// CSR
__device__ int g_cnt[NN];
__device__ int g_row[NN + 1];
__device__ int g_cur[NN];
__device__ int g_adj[EE];
// W images, transposed to [n][k] row-major bf16, hi/lo split; 6 mats
__device__ __align__(16) __nv_bfloat16 g_whi[6 * 16384];
__device__ __align__(16) __nv_bfloat16 g_wlo[6 * 16384];

__device__ __forceinline__ uint32_t smem_u32(const void* p) {
    uint32_t a;
    asm("{ .reg .u64 t; cvta.to.shared.u64 t, %1; cvt.u32.u64 %0, t; }" : "=r"(a) : "l"(p));
    return a;
}
__device__ __forceinline__ uint32_t pack2bf(__nv_bfloat16 a, __nv_bfloat16 b) {
    return (uint32_t)__bfloat16_as_ushort(a) | ((uint32_t)__bfloat16_as_ushort(b) << 16);
}
__device__ __forceinline__ void ldm_x4(uint32_t addr, uint32_t* r) {
    asm volatile("ldmatrix.sync.aligned.m8n8.x4.shared.b16 {%0,%1,%2,%3}, [%4];"
        : "=r"(r[0]), "=r"(r[1]), "=r"(r[2]), "=r"(r[3]) : "r"(addr));
}
__device__ __forceinline__ void mma_bf16(float* d, const uint32_t* a, const uint32_t* b) {
    asm volatile("mma.sync.aligned.m16n8k16.row.col.f32.bf16.bf16.f32 "
        "{%0,%1,%2,%3}, {%4,%5,%6,%7}, {%8,%9}, {%0,%1,%2,%3};"
        : "+f"(d[0]), "+f"(d[1]), "+f"(d[2]), "+f"(d[3])
        : "r"(a[0]), "r"(a[1]), "r"(a[2]), "r"(a[3]), "r"(b[0]), "r"(b[1]));
}

#define PITCH 40   // bf16 elems per smem row (80B: conflict-free ldmatrix phases)

// ---------------- CSR build ----------------
__global__ void k_zero_cnt() {
    int i = blockIdx.x * blockDim.x + threadIdx.x;
    if (i < NN) g_cnt[i] = 0;
}
__global__ void k_hist(const int* __restrict__ dst) {
    int e = blockIdx.x * blockDim.x + threadIdx.x;
    if (e < EE) atomicAdd(&g_cnt[dst[e]], 1);
}
__global__ void __launch_bounds__(1024) k_scan() {
    __shared__ int sm[1024];
    const int CH = 49;
    int t = threadIdx.x;
    int beg = t * CH;
    int tot = 0;
    for (int i = beg; i < beg + CH && i < NN; i++) tot += g_cnt[i];
    sm[t] = tot;
    __syncthreads();
    for (int off = 1; off < 1024; off <<= 1) {
        int v = (t >= off) ? sm[t - off] : 0;
        __syncthreads();
        sm[t] += v;
        __syncthreads();
    }
    int base = sm[t] - tot;
    for (int i = beg; i < beg + CH && i < NN; i++) {
        g_row[i] = base; g_cur[i] = 0; base += g_cnt[i];
    }
    if (t == 1023) g_row[NN] = sm[1023];
}
__global__ void k_fill(const int* __restrict__ src, const int* __restrict__ dst) {
    int e = blockIdx.x * blockDim.x + threadIdx.x;
    if (e >= EE) return;
    int d = dst[e];
    int pos = atomicAdd(&g_cur[d], 1);
    g_adj[g_row[d] + pos] = src[e];
}

// ---------------- weight prep: transpose to [n][k], hi/lo bf16 split ----------------
__global__ void __launch_bounds__(256) k_wprep(const float* __restrict__ W1,
                                               const float* __restrict__ W2) {
    int m = blockIdx.x;  // 0..5
    const float* src = (m < 3) ? (W1 + m * 16384) : (W2 + (m - 3) * 16384);
    __nv_bfloat16* hi = g_whi + m * 16384;
    __nv_bfloat16* lo = g_wlo + m * 16384;
    for (int i = threadIdx.x; i < 16384; i += 256) {
        int k = i >> 7, n = i & 127;       // src is W[k][n]
        float v = src[i];
        __nv_bfloat16 h = __float2bfloat16(v);
        __nv_bfloat16 l = __float2bfloat16(v - __bfloat162float(h));
        hi[n * 128 + k] = h;
        lo[n * 128 + k] = l;
    }
}

// ---------------- gather + combine (validated) ----------------
__global__ void k_gather(const float* __restrict__ Xext, int use_ext,
                         const float* __restrict__ epsp) {
    const float* X = use_ext ? Xext : (const float*)g_x;
    int gid = blockIdx.x * blockDim.x + threadIdx.x;
    int node = gid >> 5;
    if (node >= NN) return;
    int lane = gid & 31;
    int beg = g_row[node], end = g_row[node + 1];
    float4 a = make_float4(0.f, 0.f, 0.f, 0.f);
    for (int i = beg; i < end; i++) {
        int s = g_adj[i];
        float4 v = ((const float4*)X)[s * 32 + lane];
        a.x += v.x; a.y += v.y; a.z += v.z; a.w += v.w;
    }
    float4 xv = ((const float4*)X)[node * 32 + lane];
    float pa = a.x * a.x + a.y * a.y + a.z * a.z + a.w * a.w;
    float px = xv.x * xv.x + xv.y * xv.y + xv.z * xv.z + xv.w * xv.w;
    #pragma unroll
    for (int off = 16; off; off >>= 1) {
        pa += __shfl_xor_sync(0xffffffffu, pa, off);
        px += __shfl_xor_sync(0xffffffffu, px, off);
    }
    float ia = 1.f / fmaxf(sqrtf(pa), 1e-12f);
    float ix = (1.f + epsp[0]) / fmaxf(sqrtf(px), 1e-12f);
    float4 o;
    o.x = a.x * ia + xv.x * ix;
    o.y = a.y * ia + xv.y * ix;
    o.z = a.z * ia + xv.z * ix;
    o.w = a.w * ia + xv.w * ix;
    ((float4*)g_comb)[node * 32 + lane] = o;
}

// ---------------- GEMM core pieces ----------------
// X chunk (32 k-cols) into hi/lo smem planes. mode 0: g_comb; mode 1: bn_relu(g_h)
__device__ __forceinline__ void load_xchunk(ushortt* Xhi, ushortt* Xlo,
                                            int row0, int ck, int mode) {
    int t = threadIdx.x;
    int r = t >> 1, c0 = (t & 1) * 16;
    int gr = row0 + r;
    int gc = ck * 32 + c0;
    uint32_t hp[8], lp[8];
    if (gr < NN) {
        const float* src = (mode ? g_h : g_comb) + gr * DD + gc;
        #pragma unroll
        for (int i = 0; i < 8; i++) {
            float v0 = src[2 * i], v1 = src[2 * i + 1];
            if (mode) {
                v0 = fmaxf(fmaf(v0, g_scale[gc + 2 * i], g_shift[gc + 2 * i]), 0.f);
                v1 = fmaxf(fmaf(v1, g_scale[gc + 2 * i + 1], g_shift[gc + 2 * i + 1]), 0.f);
            }
            __nv_bfloat16 h0 = __float2bfloat16(v0), h1 = __float2bfloat16(v1);
            __nv_bfloat16 l0 = __float2bfloat16(v0 - __bfloat162float(h0));
            __nv_bfloat16 l1 = __float2bfloat16(v1 - __bfloat162float(h1));
            hp[i] = pack2bf(h0, h1);
            lp[i] = pack2bf(l0, l1);
        }
    } else {
        #pragma unroll
        for (int i = 0; i < 8; i++) { hp[i] = 0; lp[i] = 0; }
    }
    uint4* dh = (uint4*)(Xhi + r * PITCH + c0);
    uint4* dl = (uint4*)(Xlo + r * PITCH + c0);
    dh[0] = make_uint4(hp[0], hp[1], hp[2], hp[3]);
    dh[1] = make_uint4(hp[4], hp[5], hp[6], hp[7]);
    dl[0] = make_uint4(lp[0], lp[1], lp[2], lp[3]);
    dl[1] = make_uint4(lp[4], lp[5], lp[6], lp[7]);
}

__device__ __forceinline__ void load_wchunk(ushortt* Whi, ushortt* Wlo, int mat, int ck) {
    int t = threadIdx.x;
    int r = t >> 1, c0 = (t & 1) * 16;
    const uint4* sh = (const uint4*)(g_whi + mat * 16384 + r * 128 + ck * 32 + c0);
    const uint4* sl = (const uint4*)(g_wlo + mat * 16384 + r * 128 + ck * 32 + c0);
    uint4* dh = (uint4*)(Whi + r * PITCH + c0);
    uint4* dl = (uint4*)(Wlo + r * PITCH + c0);
    dh[0] = sh[0]; dh[1] = sh[1];
    dl[0] = sl[0]; dl[1] = sl[1];
}

// one k-chunk x one pass of MMAs for this warp
__device__ __forceinline__ void do_pass(const ushortt* A, const ushortt* B,
                                        int wm, int wn, int lane, float acc[4][4][4]) {
    uint32_t abase = smem_u32(A);
    uint32_t bbase = smem_u32(B);
    #pragma unroll
    for (int ks = 0; ks < 2; ks++) {
        uint32_t af[4][4];
        #pragma unroll
        for (int mt = 0; mt < 4; mt++) {
            int row = wm * 64 + mt * 16 + (lane & 7) + ((lane >> 3) & 1) * 8;
            int col = ks * 16 + ((lane >> 4) & 1) * 8;
            ldm_x4(abase + (row * PITCH + col) * 2, af[mt]);
        }
        uint32_t bf[4][2];
        #pragma unroll
        for (int jp = 0; jp < 2; jp++) {   // n-tile pairs (0,1),(2,3)
            int n = wn * 32 + jp * 16 + ((lane >> 4) & 1) * 8 + (lane & 7);
            int col = ks * 16 + ((lane >> 3) & 1) * 8;
            uint32_t r4[4];
            ldm_x4(bbase + (n * PITCH + col) * 2, r4);
            bf[jp * 2][0] = r4[0]; bf[jp * 2][1] = r4[1];
            bf[jp * 2 + 1][0] = r4[2]; bf[jp * 2 + 1][1] = r4[3];
        }
        #pragma unroll
        for (int mt = 0; mt < 4; mt++)
            #pragma unroll
            for (int nt = 0; nt < 4; nt++)
                mma_bf16(acc[mt][nt], af[mt], bf[nt]);
    }
}

__device__ __forceinline__ void gemm_mainloop(ushortt* sXhi, ushortt* sXlo,
                                              ushortt* sWhi, ushortt* sWlo,
                                              int row0, int mode, int mat,
                                              int wm, int wn, int lane,
                                              float acc[4][4][4]) {
    for (int ck = 0; ck < 4; ck++) {
        __syncthreads();
        load_xchunk(sXhi, sXlo, row0, ck, mode);
        load_wchunk(sWhi, sWlo, mat, ck);
        __syncthreads();
        do_pass(sXhi, sWhi, wm, wn, lane, acc);   // hi*hi
        do_pass(sXhi, sWlo, wm, wn, lane, acc);   // hi*lo
        do_pass(sXlo, sWhi, wm, wn, lane, acc);   // lo*hi
    }
}

// ---------------- GEMM1: h = comb @ W1 + b1 -> g_h, BN partials ----------------
__global__ void __launch_bounds__(256) k_gemm1_mma(int mat, const float* __restrict__ b) {
    __shared__ __align__(16) ushortt sXhi[128 * PITCH];
    __shared__ __align__(16) ushortt sXlo[128 * PITCH];
    __shared__ __align__(16) ushortt sWhi[128 * PITCH];
    __shared__ __align__(16) ushortt sWlo[128 * PITCH];
    int tid = threadIdx.x;
    int wid = tid >> 5, lane = tid & 31;
    int wm = wid & 1, wn = wid >> 1;
    int row0 = blockIdx.x * 128;

    float acc[4][4][4];
    #pragma unroll
    for (int mt = 0; mt < 4; mt++)
        #pragma unroll
        for (int nt = 0; nt < 4; nt++)
            #pragma unroll
            for (int i = 0; i < 4; i++) acc[mt][nt][i] = 0.f;

    gemm_mainloop(sXhi, sXlo, sWhi, sWlo, row0, 0, mat, wm, wn, lane, acc);

    // epilogue: bias add, store h, thread-local stats
    float ls[4][2], lq[4][2];
    #pragma unroll
    for (int nt = 0; nt < 4; nt++) { ls[nt][0] = ls[nt][1] = lq[nt][0] = lq[nt][1] = 0.f; }
    #pragma unroll
    for (int mt = 0; mt < 4; mt++) {
        int r0 = row0 + wm * 64 + mt * 16 + (lane >> 2);
        int r1 = r0 + 8;
        #pragma unroll
        for (int nt = 0; nt < 4; nt++) {
            int c = wn * 32 + nt * 8 + (lane & 3) * 2;
            float b0 = b[c], b1 = b[c + 1];
            float v0 = acc[mt][nt][0] + b0, v1 = acc[mt][nt][1] + b1;
            float v2 = acc[mt][nt][2] + b0, v3 = acc[mt][nt][3] + b1;
            if (r0 < NN) {
                *(float2*)(g_h + r0 * DD + c) = make_float2(v0, v1);
                ls[nt][0] += v0; ls[nt][1] += v1;
                lq[nt][0] += v0 * v0; lq[nt][1] += v1 * v1;
            }
            if (r1 < NN) {
                *(float2*)(g_h + r1 * DD + c) = make_float2(v2, v3);
                ls[nt][0] += v2; ls[nt][1] += v3;
                lq[nt][0] += v2 * v2; lq[nt][1] += v3 * v3;
            }
        }
    }
    // reduce across the 8 row-groups (lanes differing in bits 2..4)
    #pragma unroll
    for (int off = 4; off <= 16; off <<= 1) {
        #pragma unroll
        for (int nt = 0; nt < 4; nt++) {
            ls[nt][0] += __shfl_xor_sync(0xffffffffu, ls[nt][0], off);
            ls[nt][1] += __shfl_xor_sync(0xffffffffu, ls[nt][1], off);
            lq[nt][0] += __shfl_xor_sync(0xffffffffu, lq[nt][0], off);
            lq[nt][1] += __shfl_xor_sync(0xffffffffu, lq[nt][1], off);
        }
    }
    __syncthreads();   // done with smem planes; reuse sXhi for stats
    float* ssum = (float*)sXhi;          // [8][32]
    float* ssq  = ssum + 256;
    if (lane < 4) {
        #pragma unroll
        for (int nt = 0; nt < 4; nt++) {
            ssum[wid * 32 + nt * 8 + lane * 2]     = ls[nt][0];
            ssum[wid * 32 + nt * 8 + lane * 2 + 1] = ls[nt][1];
            ssq[wid * 32 + nt * 8 + lane * 2]      = lq[nt][0];
            ssq[wid * 32 + nt * 8 + lane * 2 + 1]  = lq[nt][1];
        }
    }
    __syncthreads();
    if (tid < DD) {
        int w0 = (tid >> 5) * 2;        // warps with wn = tid/32: wid = wn*2 + {0,1}
        float s = ssum[w0 * 32 + (tid & 31)] + ssum[(w0 + 1) * 32 + (tid & 31)];
        float q = ssq[w0 * 32 + (tid & 31)] + ssq[(w0 + 1) * 32 + (tid & 31)];
        g_psum[blockIdx.x * DD + tid] = s;
        g_psumsq[blockIdx.x * DD + tid] = q;
    }
}

// ---------------- finalize BN ----------------
__global__ void __launch_bounds__(256) k_finalize(const float* __restrict__ gamma,
                                                  const float* __restrict__ beta) {
    __shared__ float ss[256], sq[256];
    int c = blockIdx.x;
    int t = threadIdx.x;
    float s = 0.f, q = 0.f;
    for (int bk = t; bk < NBT; bk += 256) {
        s += g_psum[bk * DD + c];
        q += g_psumsq[bk * DD + c];
    }
    ss[t] = s; sq[t] = q;
    __syncthreads();
    for (int off = 128; off; off >>= 1) {
        if (t < off) { ss[t] += ss[t + off]; sq[t] += sq[t + off]; }
        __syncthreads();
    }
    if (t == 0) {
        float mean = ss[0] * (1.f / NN);
        float var  = sq[0] * (1.f / NN) - mean * mean;
        float sc = gamma[c] * rsqrtf(var + 1e-5f);
        g_scale[c] = sc;
        g_shift[c] = beta[c] - mean * sc;
    }
}

// ---------------- GEMM2: out = relu?(bn_relu(h) @ W2 + b2) ----------------
__global__ void __launch_bounds__(256) k_gemm2_mma(int mat, const float* __restrict__ b,
                                                   float* __restrict__ OutExt,
                                                   int internal, int do_relu) {
    __shared__ __align__(16) ushortt sXhi[128 * PITCH];
    __shared__ __align__(16) ushortt sXlo[128 * PITCH];
    __shared__ __align__(16) ushortt sWhi[128 * PITCH];
    __shared__ __align__(16) ushortt sWlo[128 * PITCH];
    float* Out = internal ? (float*)g_x : OutExt;
    int tid = threadIdx.x;
    int wid = tid >> 5, lane = tid & 31;
    int wm = wid & 1, wn = wid >> 1;
    int row0 = blockIdx.x * 128;

    float acc[4][4][4];
    #pragma unroll
    for (int mt = 0; mt < 4; mt++)
        #pragma unroll
        for (int nt = 0; nt < 4; nt++)
            #pragma unroll
            for (int i = 0; i < 4; i++) acc[mt][nt][i] = 0.f;

    gemm_mainloop(sXhi, sXlo, sWhi, sWlo, row0, 1, mat, wm, wn, lane, acc);

    #pragma unroll
    for (int mt = 0; mt < 4; mt++) {
        int r0 = row0 + wm * 64 + mt * 16 + (lane >> 2);
        int r1 = r0 + 8;
        #pragma unroll
        for (int nt = 0; nt < 4; nt++) {
            int c = wn * 32 + nt * 8 + (lane & 3) * 2;
            float b0 = b[c], b1 = b[c + 1];
            float v0 = acc[mt][nt][0] + b0, v1 = acc[mt][nt][1] + b1;
            float v2 = acc[mt][nt][2] + b0, v3 = acc[mt][nt][3] + b1;
            if (do_relu) {
                v0 = fmaxf(v0, 0.f); v1 = fmaxf(v1, 0.f);
                v2 = fmaxf(v2, 0.f); v3 = fmaxf(v3, 0.f);
            }
            if (r0 < NN) *(float2*)(Out + r0 * DD + c) = make_float2(v0, v1);
            if (r1 < NN) *(float2*)(Out + r1 * DD + c) = make_float2(v2, v3);
        }
    }
}

extern "C" void kernel_launch(void* const* d_in, const int* in_sizes, int n_in,
                              void* d_out, int out_size) {
    (void)in_sizes; (void)n_in; (void)out_size;
    const float* x     = (const float*)d_in[0];
    const int*   ei    = (const int*)d_in[1];   // int32 (JAX x64 disabled)
    const float* W1    = (const float*)d_in[2];
    const float* b1    = (const float*)d_in[3];
    const float* gamma = (const float*)d_in[4];
    const float* beta  = (const float*)d_in[5];
    const float* W2    = (const float*)d_in[6];
    const float* b2    = (const float*)d_in[7];
    const float* eps   = (const float*)d_in[8];
    float* out = (float*)d_out;

    const int* src = ei;
    const int* dst = ei + EE;

    // CSR + weight prep (once, reused across layers)
    k_zero_cnt<<<(NN + 255) / 256, 256>>>();
    k_hist<<<(EE + 255) / 256, 256>>>(dst);
    k_scan<<<1, 1024>>>();
    k_fill<<<(EE + 255) / 256, 256>>>(src, dst);
    k_wprep<<<6, 256>>>(W1, W2);

    for (int l = 0; l < 3; l++) {
        int use_ext = (l == 0) ? 1 : 0;
        int internal = (l == 2) ? 0 : 1;
        k_gather<<<(NN * 32 + 255) / 256, 256>>>(x, use_ext, eps + l);
        k_gemm1_mma<<<NBT, 256>>>(l, b1 + l * DD);
        k_finalize<<<DD, 256>>>(gamma + l * DD, beta + l * DD);
        k_gemm2_mma<<<NBT, 256>>>(3 + l, b2 + l * DD, out, internal, (l < 2) ? 1 : 0);
    }
}